// round 8
// baseline (speedup 1.0000x reference)
#include <cuda_runtime.h>

// ---------------------------------------------------------------------------
// LieSpline: SE(3) cubic B-spline interpolation.  B=32, N=2048, K=32.  FUSED.
//
// One kernel.  Block = 8 warps = 16 consecutive segments of one batch.
// Phase 1: lanes 0..17 of warp 0 compute the 18 delta records the block
//   needs (se3_log of consecutive relative poses + lane-invariant exp
//   precomputes + base pose) into shared memory (5 float4 each):
//     r0 = (tau.xyz | nd)
//     r1 = (U.xyz   | C1'.x)      C1' = (2/nd^2) * cross(phi,tau)
//     r2 = (C1'.y, C1'.z, C2'.x, C2'.y)  C2' = (1/nd^3)*cross(phi,cross(phi,tau))
//     r3 = (C2'.z, pose_t.xyz)
//     r4 = pose_q
// Phase 2: warp w handles segments s0 = s_base+2w, s0+1; lane = time sample.
//   exp(w*d): theta=w*nd; sincos(theta/2); alpha=sh^2; beta=theta-2*sh*ch;
//     At = w*tau + alpha*C1' + beta*C2' ; Aq = (sh*U, ch);  T <- T*A.
//   Records read via uniform LDS (broadcast), serial-interleaved consumption.
// ---------------------------------------------------------------------------

#define LS_B 32
#define LS_N 2048
#define LS_S (LS_N - 1)     // 2047 segments
#define SEG_PER_BLK 16
#define BLK_PER_B 128       // 128 * 16 = 2048 >= 2047
#define NREC 18             // records s_base .. s_base+17

__device__ __forceinline__ float3 f3(float x, float y, float z) {
    return make_float3(x, y, z);
}
__device__ __forceinline__ float3 cross3(const float3 a, const float3 b) {
    return make_float3(a.y * b.z - a.z * b.y,
                       a.z * b.x - a.x * b.z,
                       a.x * b.y - a.y * b.x);
}
__device__ __forceinline__ float dot3(const float3 a, const float3 b) {
    return a.x * b.x + a.y * b.y + a.z * b.z;
}
__device__ __forceinline__ float3 qrot(const float4 q, const float3 v) {
    float3 qv = f3(q.x, q.y, q.z);
    float3 t = cross3(qv, v);
    t.x *= 2.0f; t.y *= 2.0f; t.z *= 2.0f;
    float3 c = cross3(qv, t);
    return f3(v.x + q.w * t.x + c.x,
              v.y + q.w * t.y + c.y,
              v.z + q.w * t.z + c.z);
}
__device__ __forceinline__ float4 qmul(const float4 a, const float4 b) {
    return make_float4(
        a.w * b.x + a.x * b.w + a.y * b.z - a.z * b.y,
        a.w * b.y + a.y * b.w + a.z * b.x - a.x * b.z,
        a.w * b.z + a.z * b.w + a.x * b.y - a.y * b.x,
        a.w * b.w - a.x * b.x - a.y * b.y - a.z * b.z);
}

struct Xf { float3 t; float4 q; };

// exp + in-place right-compose: T <- T * exp(wk * delta)
// record fields: r0 = tau|nd, r1 = U|C1'x, r2 = C1'yz C2'xy, c2z = C2'z
__device__ __forceinline__ void stepc(Xf& T,
                                      const float4 r0, const float4 r1,
                                      const float4 r2, float c2z,
                                      float wk) {
    float theta = wk * r0.w;
    float sh, ch;
    __sincosf(0.5f * theta, &sh, &ch);
    float alpha = sh * sh;                        // (1 - cos th) with K2 premult
    float beta  = fmaf(-(sh + sh), ch, theta);    // th - sin th  with rn3 premult
    float3 At;
    At.x = fmaf(beta, r2.z, fmaf(alpha, r1.w, wk * r0.x));
    At.y = fmaf(beta, r2.w, fmaf(alpha, r2.x, wk * r0.y));
    At.z = fmaf(beta, c2z,  fmaf(alpha, r2.y, wk * r0.z));
    float4 Aq = make_float4(sh * r1.x, sh * r1.y, sh * r1.z, ch);
    float3 r = qrot(T.q, At);
    T.t.x += r.x; T.t.y += r.y; T.t.z += r.z;
    T.q = qmul(T.q, Aq);
}

// ---------------------------------------------------------------------------
__global__ void __launch_bounds__(256) k_fused(const float* __restrict__ poses,
                                               const float* __restrict__ timev,
                                               float* __restrict__ out) {
    __shared__ __align__(16) float4 rec[NREC * 5];
    __shared__ __align__(16) float  stg[8 * 448];

    const unsigned b      = blockIdx.y;
    const unsigned s_base = blockIdx.x * SEG_PER_BLK;
    const unsigned tid    = threadIdx.x;
    const float* pbase = poses + b * (LS_N * 7);

    // ---------------- Phase 1: delta records into shared ----------------
    if (tid < NREC) {
        unsigned j = s_base + tid;       // delta index, valid if <= LS_N
        if (j <= LS_N) {
            float4* o = rec + tid * 5;
            unsigned pj = j > 0 ? j - 1 : 0;
            const float* pr = pbase + pj * 7;
            float3 t0 = f3(pr[0], pr[1], pr[2]);
            float4 q0 = make_float4(pr[3], pr[4], pr[5], pr[6]);
            o[4] = q0;
            if (j == 0 || j == LS_N) {
                o[0] = make_float4(0.f, 0.f, 0.f, 0.f);
                o[1] = make_float4(0.f, 0.f, 0.f, 0.f);
                o[2] = make_float4(0.f, 0.f, 0.f, 0.f);
                o[3] = make_float4(0.f, t0.x, t0.y, t0.z);
            } else {
                const float* pr1 = pr + 7;
                float3 t1 = f3(pr1[0], pr1[1], pr1[2]);
                float4 q1 = make_float4(pr1[3], pr1[4], pr1[5], pr1[6]);

                float4 qi = make_float4(-q0.x, -q0.y, -q0.z, q0.w);
                float3 dt = f3(t1.x - t0.x, t1.y - t0.y, t1.z - t0.z);
                float3 t  = qrot(qi, dt);
                float4 q  = qmul(qi, q1);

                // so3_log
                float n2 = q.x * q.x + q.y * q.y + q.z * q.z;
                bool small = n2 < 1e-12f;
                float ns = small ? 1.0f : n2;
                float rn = rsqrtf(ns);
                float n  = ns * rn;
                float factor;
                if (small) {
                    float iw = __fdividef(1.0f, q.w);
                    factor = 2.0f * iw - (2.0f / 3.0f) * n2 * iw * iw * iw;
                } else {
                    factor = 2.0f * atan2f(n, q.w) * rn;
                }
                float3 phi = f3(factor * q.x, factor * q.y, factor * q.z);

                // jl_inv
                float t2 = dot3(phi, phi);
                bool sm2 = t2 < 1e-12f;
                float t2s = sm2 ? 1.0f : t2;
                float rth = rsqrtf(t2s);
                float theta = t2s * rth;
                float s, cth;
                __sincosf(theta, &s, &cth);
                float s_safe = (fabsf(s) < 1e-6f) ? 1e-6f : s;
                float c;
                if (sm2) {
                    c = (1.0f / 12.0f) + t2 * (1.0f / 720.0f);
                } else {
                    c = rth * rth - __fdividef(1.0f + cth, 2.0f * theta * s_safe);
                }
                float3 x1 = cross3(phi, t);
                float3 x2 = cross3(phi, x1);
                float3 tau = f3(t.x - 0.5f * x1.x + c * x2.x,
                                t.y - 0.5f * x1.y + c * x2.y,
                                t.z - 0.5f * x1.z + c * x2.z);

                float nd2 = dot3(phi, phi);
                if (nd2 < 1e-24f) {
                    o[0] = make_float4(tau.x, tau.y, tau.z, 0.f);
                    o[1] = make_float4(0.f, 0.f, 0.f, 0.f);
                    o[2] = make_float4(0.f, 0.f, 0.f, 0.f);
                    o[3] = make_float4(0.f, t0.x, t0.y, t0.z);
                } else {
                    float rnd = rsqrtf(nd2);
                    float nd  = nd2 * rnd;
                    float K2  = 2.0f * rnd * rnd;
                    float rn3 = rnd * rnd * rnd;
                    float3 U  = f3(phi.x * rnd, phi.y * rnd, phi.z * rnd);
                    float3 C1 = cross3(phi, tau);
                    float3 C2 = cross3(phi, C1);
                    C1.x *= K2;  C1.y *= K2;  C1.z *= K2;
                    C2.x *= rn3; C2.y *= rn3; C2.z *= rn3;
                    o[0] = make_float4(tau.x, tau.y, tau.z, nd);
                    o[1] = make_float4(U.x, U.y, U.z, C1.x);
                    o[2] = make_float4(C1.y, C1.z, C2.x, C2.y);
                    o[3] = make_float4(C2.z, t0.x, t0.y, t0.z);
                }
            }
        }
    }
    __syncthreads();

    // ---------------- Phase 2: spline evaluation ----------------
    const unsigned w    = tid >> 5;
    const unsigned lane = tid & 31;
    const unsigned s0   = s_base + 2 * w;
    const bool tail = (s0 + 1 >= LS_S);   // s0 == 2046

    float u  = __ldg(timev + lane);
    float u2 = u * u;
    float u3 = u2 * u;
    const float w0 = (5.0f + 3.0f * u - 3.0f * u2 + u3) * (1.0f / 6.0f);
    const float w1 = (1.0f + 3.0f * u + 3.0f * u2 - 2.0f * u3) * (1.0f / 6.0f);
    const float w2 = u3 * (1.0f / 6.0f);

    const float4* R = rec + (2 * w) * 5;   // record s0 (warp-uniform smem)

    // record s0: T0 = P0 * exp(w0 * d0)
    Xf T0;
    {
        float4 r0 = R[0], r1 = R[1], r2 = R[2], r3 = R[3], r4 = R[4];
        T0.t = f3(r3.y, r3.z, r3.w);
        T0.q = r4;
        stepc(T0, r0, r1, r2, r3.x, w0);
    }
    // record s0+1: T1 = P1 * exp(w0 * d1); T0 *= exp(w1 * d1)
    Xf T1;
    {
        const float4* Rr = R + 5;
        float4 r0 = Rr[0], r1 = Rr[1], r2 = Rr[2], r3 = Rr[3], r4 = Rr[4];
        T1.t = f3(r3.y, r3.z, r3.w);
        T1.q = r4;
        stepc(T1, r0, r1, r2, r3.x, w0);
        stepc(T0, r0, r1, r2, r3.x, w1);
    }
    // record s0+2: T0 *= exp(w2 * d2) (final); T1 *= exp(w1 * d2)
    {
        const float4* Rr = R + 10;
        float4 r0 = Rr[0], r1 = Rr[1], r2 = Rr[2];
        float c2z = Rr[3].x;
        stepc(T0, r0, r1, r2, c2z, w2);
        stepc(T1, r0, r1, r2, c2z, w1);
    }
    // record s0+3 (clamped on tail): T1 *= exp(w2 * d3) (final)
    {
        const float4* Rr = R + (tail ? 10 : 15);
        float4 r0 = Rr[0], r1 = Rr[1], r2 = Rr[2];
        float c2z = Rr[3].x;
        stepc(T1, r0, r1, r2, c2z, w2);
    }

    // stage through shared; 448 contiguous floats per warp
    float* smw  = stg + w * 448;
    float* smw2 = smw + 224;
    unsigned o7 = lane * 7;
    smw[o7 + 0] = T0.t.x; smw[o7 + 1] = T0.t.y; smw[o7 + 2] = T0.t.z;
    smw[o7 + 3] = T0.q.x; smw[o7 + 4] = T0.q.y; smw[o7 + 5] = T0.q.z; smw[o7 + 6] = T0.q.w;
    smw2[o7 + 0] = T1.t.x; smw2[o7 + 1] = T1.t.y; smw2[o7 + 2] = T1.t.z;
    smw2[o7 + 3] = T1.q.x; smw2[o7 + 4] = T1.q.y; smw2[o7 + 5] = T1.q.z; smw2[o7 + 6] = T1.q.w;
    __syncwarp();

    const float4* sm4 = (const float4*)smw;
    unsigned pair0 = b * LS_S + s0;
    float4* ob4 = (float4*)(out) + pair0 * 56;   // 224 floats = 56 float4
    if (!tail) {
        ob4[lane]      = sm4[lane];
        ob4[lane + 32] = sm4[lane + 32];
        ob4[lane + 64] = sm4[lane + 64];
        if (lane < 16) ob4[lane + 96] = sm4[lane + 96];
    } else {
        ob4[lane] = sm4[lane];
        if (lane < 24) ob4[lane + 32] = sm4[lane + 32];
    }
}

extern "C" void kernel_launch(void* const* d_in, const int* in_sizes, int n_in,
                              void* d_out, int out_size) {
    (void)n_in; (void)out_size;
    const float* poses = (const float*)d_in[0];
    const float* timev = (const float*)d_in[1];
    float* out = (float*)d_out;

    dim3 grid(BLK_PER_B, LS_B);
    k_fused<<<grid, 256>>>(poses, timev, out);
}

// round 9
// speedup vs baseline: 1.0115x; 1.0115x over previous
#include <cuda_runtime.h>

// ---------------------------------------------------------------------------
// LieSpline: SE(3) cubic B-spline interpolation.  B=32, N=2048, K=32.
//
// Kernel 1: per padded delta j (0..N): se3_log(inv(P[j])P[j+1]) + lane-
//   invariant exp precomputes + base pose, packed 5 float4 (80B) per record:
//     r0 = (tau.xyz | nd)
//     r1 = (U.xyz   | C1'.x)      C1' = (2/nd^2) * cross(phi,tau)
//     r2 = (C1'.y, C1'.z, C2'.x, C2'.y)  C2' = (1/nd^3)*cross(phi,cross(phi,tau))
//     r3 = (C2'.z, pose_t.xyz)
//     r4 = pose_q
// Kernel 2: warp = (b, 2 consecutive segments), lane = time sample (K==32).
//   The warp's 4 records are 320 CONTIGUOUS bytes -> ONE cooperative LDG.128
//   by lanes 0..19 into per-warp smem (MLP=20 in a single instruction), then
//   phase 2 consumes them as cheap uniform LDS broadcasts.  Removes the
//   serial L2-latency chain that capped issue at 68%.
// ---------------------------------------------------------------------------

#define LS_B 32
#define LS_N 2048
#define LS_J (LS_N + 1)   // 2049 deltas per batch
#define REC 5             // float4s per delta record
#define LS_S (LS_N - 1)   // 2047 segments
#define LS_M 1024         // segment-pairs per batch

__device__ float4 g_pre[LS_B * LS_J * REC];   // 5.2 MB scratch

__device__ __forceinline__ float3 f3(float x, float y, float z) {
    return make_float3(x, y, z);
}
__device__ __forceinline__ float3 cross3(const float3 a, const float3 b) {
    return make_float3(a.y * b.z - a.z * b.y,
                       a.z * b.x - a.x * b.z,
                       a.x * b.y - a.y * b.x);
}
__device__ __forceinline__ float dot3(const float3 a, const float3 b) {
    return a.x * b.x + a.y * b.y + a.z * b.z;
}
__device__ __forceinline__ float3 qrot(const float4 q, const float3 v) {
    float3 qv = f3(q.x, q.y, q.z);
    float3 t = cross3(qv, v);
    t.x *= 2.0f; t.y *= 2.0f; t.z *= 2.0f;
    float3 c = cross3(qv, t);
    return f3(v.x + q.w * t.x + c.x,
              v.y + q.w * t.y + c.y,
              v.z + q.w * t.z + c.z);
}
__device__ __forceinline__ float4 qmul(const float4 a, const float4 b) {
    return make_float4(
        a.w * b.x + a.x * b.w + a.y * b.z - a.z * b.y,
        a.w * b.y + a.y * b.w + a.z * b.x - a.x * b.z,
        a.w * b.z + a.z * b.w + a.x * b.y - a.y * b.x,
        a.w * b.w - a.x * b.x - a.y * b.y - a.z * b.z);
}

// ---------------------------------------------------------------------------
// Kernel 1: per-(b, j) relative-pose log + precompute
// ---------------------------------------------------------------------------
__global__ void __launch_bounds__(256) k_delta(const float* __restrict__ poses) {
    unsigned idx = blockIdx.x * blockDim.x + threadIdx.x;
    if (idx >= LS_B * LS_J) return;
    unsigned b = idx / LS_J;
    unsigned j = idx - b * LS_J;
    float4* o = g_pre + idx * REC;
    const float* pbase = poses + b * (LS_N * 7);

    unsigned pj = j > 0 ? j - 1 : 0;
    const float* pr = pbase + pj * 7;
    float3 t0 = f3(pr[0], pr[1], pr[2]);
    float4 q0 = make_float4(pr[3], pr[4], pr[5], pr[6]);
    o[4] = q0;

    if (j == 0 || j == LS_N) {
        float4 z = make_float4(0.f, 0.f, 0.f, 0.f);
        o[0] = z; o[1] = z; o[2] = z;
        o[3] = make_float4(0.f, t0.x, t0.y, t0.z);
        return;
    }
    const float* pr1 = pr + 7;
    float3 t1 = f3(pr1[0], pr1[1], pr1[2]);
    float4 q1 = make_float4(pr1[3], pr1[4], pr1[5], pr1[6]);

    float4 qi = make_float4(-q0.x, -q0.y, -q0.z, q0.w);
    float3 dt = f3(t1.x - t0.x, t1.y - t0.y, t1.z - t0.z);
    float3 t  = qrot(qi, dt);
    float4 q  = qmul(qi, q1);

    float n2 = q.x * q.x + q.y * q.y + q.z * q.z;
    bool small = n2 < 1e-12f;
    float ns = small ? 1.0f : n2;
    float rn = rsqrtf(ns);
    float n  = ns * rn;
    float factor;
    if (small) {
        float iw = __fdividef(1.0f, q.w);
        factor = 2.0f * iw - (2.0f / 3.0f) * n2 * iw * iw * iw;
    } else {
        factor = 2.0f * atan2f(n, q.w) * rn;
    }
    float3 phi = f3(factor * q.x, factor * q.y, factor * q.z);

    float t2 = dot3(phi, phi);
    bool sm2 = t2 < 1e-12f;
    float t2s = sm2 ? 1.0f : t2;
    float rth = rsqrtf(t2s);
    float theta = t2s * rth;
    float s, cth;
    __sincosf(theta, &s, &cth);
    float s_safe = (fabsf(s) < 1e-6f) ? 1e-6f : s;
    float c;
    if (sm2) {
        c = (1.0f / 12.0f) + t2 * (1.0f / 720.0f);
    } else {
        c = rth * rth - __fdividef(1.0f + cth, 2.0f * theta * s_safe);
    }
    float3 x1 = cross3(phi, t);
    float3 x2 = cross3(phi, x1);
    float3 tau = f3(t.x - 0.5f * x1.x + c * x2.x,
                    t.y - 0.5f * x1.y + c * x2.y,
                    t.z - 0.5f * x1.z + c * x2.z);

    float nd2 = dot3(phi, phi);
    if (nd2 < 1e-24f) {
        o[0] = make_float4(tau.x, tau.y, tau.z, 0.f);
        o[1] = make_float4(0.f, 0.f, 0.f, 0.f);
        o[2] = make_float4(0.f, 0.f, 0.f, 0.f);
        o[3] = make_float4(0.f, t0.x, t0.y, t0.z);
        return;
    }
    float rnd = rsqrtf(nd2);         // 1/nd
    float nd  = nd2 * rnd;           // |phi|
    float K2  = 2.0f * rnd * rnd;    // 2/nd^2
    float rn3 = rnd * rnd * rnd;     // 1/nd^3
    float3 U  = f3(phi.x * rnd, phi.y * rnd, phi.z * rnd);
    float3 C1 = cross3(phi, tau);
    float3 C2 = cross3(phi, C1);
    C1.x *= K2;  C1.y *= K2;  C1.z *= K2;    // C1'
    C2.x *= rn3; C2.y *= rn3; C2.z *= rn3;   // C2'
    o[0] = make_float4(tau.x, tau.y, tau.z, nd);
    o[1] = make_float4(U.x, U.y, U.z, C1.x);
    o[2] = make_float4(C1.y, C1.z, C2.x, C2.y);
    o[3] = make_float4(C2.z, t0.x, t0.y, t0.z);
}

// ---------------------------------------------------------------------------
// exp + in-place right-compose: T <- T * exp(wk * delta)
// record fields: r0 = tau|nd, r1 = U|C1'x, r2 = C1'yz C2'xy, c2z = C2'z
// ---------------------------------------------------------------------------
struct Xf { float3 t; float4 q; };

__device__ __forceinline__ void stepc(Xf& T,
                                      const float4 r0, const float4 r1,
                                      const float4 r2, float c2z,
                                      float wk) {
    float theta = wk * r0.w;
    float sh, ch;
    __sincosf(0.5f * theta, &sh, &ch);
    float alpha = sh * sh;                        // (1 - cos th) with K2 premult
    float beta  = fmaf(-(sh + sh), ch, theta);    // th - sin th  with rn3 premult
    float3 At;
    At.x = fmaf(beta, r2.z, fmaf(alpha, r1.w, wk * r0.x));
    At.y = fmaf(beta, r2.w, fmaf(alpha, r2.x, wk * r0.y));
    At.z = fmaf(beta, c2z,  fmaf(alpha, r2.y, wk * r0.z));
    float4 Aq = make_float4(sh * r1.x, sh * r1.y, sh * r1.z, ch);
    float3 r = qrot(T.q, At);
    T.t.x += r.x; T.t.y += r.y; T.t.z += r.z;
    T.q = qmul(T.q, Aq);
}

// ---------------------------------------------------------------------------
// Kernel 2: warp = (b, segment pair m -> segments 2m, 2m+1), lane = sample k.
// ---------------------------------------------------------------------------
__global__ void __launch_bounds__(256) k_spline(const float* __restrict__ timev,
                                                float* __restrict__ out) {
    __shared__ __align__(16) float4 recbuf[8 * 20];   // 4 records/warp
    __shared__ __align__(16) float  stg[8 * 448];

    unsigned w    = threadIdx.x >> 5;
    unsigned lane = threadIdx.x & 31;
    unsigned gp = blockIdx.x * 8 + w;
    if (gp >= LS_B * LS_M) return;
    unsigned b = gp >> 10;
    unsigned m = gp & (LS_M - 1);
    unsigned s0 = 2 * m;
    bool tail = (s0 + 1 >= LS_S);

    // ---- cooperative record load: 20 contiguous float4 (records s0..s0+3)
    {
        unsigned gbase = (b * LS_J + s0) * REC;
        const unsigned GMAX = LS_B * LS_J * REC - 1;
        unsigned gidx = gbase + lane;
        if (gidx > GMAX) gidx = GMAX;       // tail clamp (loaded but unused)
        if (lane < 20) recbuf[w * 20 + lane] = g_pre[gidx];
    }
    __syncwarp();

    float u  = __ldg(timev + lane);
    float u2 = u * u;
    float u3 = u2 * u;
    const float w0 = (5.0f + 3.0f * u - 3.0f * u2 + u3) * (1.0f / 6.0f);
    const float w1 = (1.0f + 3.0f * u + 3.0f * u2 - 2.0f * u3) * (1.0f / 6.0f);
    const float w2 = u3 * (1.0f / 6.0f);

    const float4* R = recbuf + w * 20;   // warp-uniform smem

    // record s0: T0 = P0 * exp(w0 * d0)
    Xf T0;
    {
        float4 r0 = R[0], r1 = R[1], r2 = R[2], r3 = R[3], r4 = R[4];
        T0.t = f3(r3.y, r3.z, r3.w);
        T0.q = r4;
        stepc(T0, r0, r1, r2, r3.x, w0);
    }
    // record s0+1: T1 = P1 * exp(w0 * d1); T0 *= exp(w1 * d1)
    Xf T1;
    {
        const float4* Rr = R + 5;
        float4 r0 = Rr[0], r1 = Rr[1], r2 = Rr[2], r3 = Rr[3], r4 = Rr[4];
        T1.t = f3(r3.y, r3.z, r3.w);
        T1.q = r4;
        stepc(T1, r0, r1, r2, r3.x, w0);
        stepc(T0, r0, r1, r2, r3.x, w1);
    }
    // record s0+2: T0 *= exp(w2 * d2) (final); T1 *= exp(w1 * d2)
    {
        const float4* Rr = R + 10;
        float4 r0 = Rr[0], r1 = Rr[1], r2 = Rr[2];
        float c2z = Rr[3].x;
        stepc(T0, r0, r1, r2, c2z, w2);
        stepc(T1, r0, r1, r2, c2z, w1);
    }
    // record s0+3 (clamped on tail): T1 *= exp(w2 * d3) (final)
    {
        const float4* Rr = R + (tail ? 10 : 15);
        float4 r0 = Rr[0], r1 = Rr[1], r2 = Rr[2];
        float c2z = Rr[3].x;
        stepc(T1, r0, r1, r2, c2z, w2);
    }

    // stage through shared; 448 contiguous floats per warp
    float* smw  = stg + w * 448;
    float* smw2 = smw + 224;
    unsigned o7 = lane * 7;
    smw[o7 + 0] = T0.t.x; smw[o7 + 1] = T0.t.y; smw[o7 + 2] = T0.t.z;
    smw[o7 + 3] = T0.q.x; smw[o7 + 4] = T0.q.y; smw[o7 + 5] = T0.q.z; smw[o7 + 6] = T0.q.w;
    smw2[o7 + 0] = T1.t.x; smw2[o7 + 1] = T1.t.y; smw2[o7 + 2] = T1.t.z;
    smw2[o7 + 3] = T1.q.x; smw2[o7 + 4] = T1.q.y; smw2[o7 + 5] = T1.q.z; smw2[o7 + 6] = T1.q.w;
    __syncwarp();

    const float4* sm4 = (const float4*)smw;
    unsigned pair0 = b * LS_S + s0;
    float4* ob4 = (float4*)(out) + pair0 * 56;   // 224 floats = 56 float4
    if (!tail) {
        ob4[lane]      = sm4[lane];
        ob4[lane + 32] = sm4[lane + 32];
        ob4[lane + 64] = sm4[lane + 64];
        if (lane < 16) ob4[lane + 96] = sm4[lane + 96];
    } else {
        ob4[lane] = sm4[lane];
        if (lane < 24) ob4[lane + 32] = sm4[lane + 32];
    }
}

extern "C" void kernel_launch(void* const* d_in, const int* in_sizes, int n_in,
                              void* d_out, int out_size) {
    (void)n_in; (void)out_size;
    const float* poses = (const float*)d_in[0];
    const float* timev = (const float*)d_in[1];
    float* out = (float*)d_out;

    int tot1 = LS_B * LS_J;
    k_delta<<<(tot1 + 255) / 256, 256>>>(poses);

    int tot2 = LS_B * LS_M;
    k_spline<<<(tot2 + 7) / 8, 256>>>(timev, out);
}